// round 1
// baseline (speedup 1.0000x reference)
#include <cuda_runtime.h>
#include <math.h>

// Problem constants
#define Jc 166
#define Rc 864
#define Oc 8
#define Bc 128
#define BT 8            // batches per CTA
#define TT 288          // threads per CTA (864 / 3)
#define KR 3            // routes (r) per thread
#define NW 9            // warps per CTA

// smem layout (in floats)
#define UH_FLOATS   (BT * 2 * Rc * 4)         // 55296 : u_hat as 2 float4-planes per batch
#define RED0_OFF    (UH_FLOATS)               // [NW][64] gen-pass s0 partials
#define SRED_OFF    (RED0_OFF + NW * 64)      // [64]     reduced s0
#define RMAX_OFF    (SRED_OFF + 64)           // [16]     per-warp max
#define RSUM_OFF    (RMAX_OFF + 16)           // [NW][10] per-warp {svec[8], sum_t}
#define SMEM_FLOATS (RSUM_OFF + NW * 10)
#define SMEM_BYTES  (SMEM_FLOATS * 4)

__device__ __forceinline__ float wsum(float v) {
#pragma unroll
    for (int s = 16; s; s >>= 1) v += __shfl_xor_sync(0xffffffffu, v, s);
    return v;
}
__device__ __forceinline__ float wmax(float v) {
#pragma unroll
    for (int s = 16; s; s >>= 1) v = fmaxf(v, __shfl_xor_sync(0xffffffffu, v, s));
    return v;
}

__global__ void __launch_bounds__(TT, 1)
digitcaps_kernel(const float* __restrict__ u,
                 const float* __restrict__ W,
                 float* __restrict__ out)
{
    extern __shared__ float sm[];
    float4* uh4  = (float4*)sm;              // [BT*2*Rc] float4
    float* red0  = sm + RED0_OFF;
    float* sred  = sm + SRED_OFF;
    float* rmax  = sm + RMAX_OFF;
    float* rsum  = sm + RSUM_OFF;

    const int j    = blockIdx.x;
    const int b0   = blockIdx.y * BT;
    const int t    = threadIdx.x;
    const int warp = t >> 5;
    const int lane = t & 31;

    const float4* __restrict__ Wj = ((const float4*)W) + (size_t)j * (Rc * Oc);
    const float4* __restrict__ u4 = (const float4*)u;

    // ---------------- gen: u_hat -> smem, fused s0 accumulation ----------------
    float s0[BT][Oc];
#pragma unroll
    for (int b = 0; b < BT; b++)
#pragma unroll
        for (int o = 0; o < Oc; o++) s0[b][o] = 0.f;

#pragma unroll
    for (int k = 0; k < KR; k++) {
        const int r = t + k * TT;
        float4 w[Oc];
#pragma unroll
        for (int o = 0; o < Oc; o++) w[o] = Wj[r * Oc + o];
#pragma unroll
        for (int b = 0; b < BT; b++) {
            const float4 uu = u4[(size_t)(b0 + b) * Rc + r];
            float uh[Oc];
#pragma unroll
            for (int o = 0; o < Oc; o++)
                uh[o] = w[o].x * uu.x + w[o].y * uu.y + w[o].z * uu.z + w[o].w * uu.w;
            uh4[(b * 2 + 0) * Rc + r] = make_float4(uh[0], uh[1], uh[2], uh[3]);
            uh4[(b * 2 + 1) * Rc + r] = make_float4(uh[4], uh[5], uh[6], uh[7]);
#pragma unroll
            for (int o = 0; o < Oc; o++) s0[b][o] += uh[o];
        }
    }

    // reduce the 64 s0 accumulators block-wide
#pragma unroll
    for (int b = 0; b < BT; b++)
#pragma unroll
        for (int o = 0; o < Oc; o++) {
            const float v = wsum(s0[b][o]);
            if (lane == 0) red0[warp * 64 + b * 8 + o] = v;
        }
    __syncthreads();
    if (t < 64) {
        float acc = 0.f;
#pragma unroll
        for (int w2 = 0; w2 < NW; w2++) acc += red0[w2 * 64 + t];
        sred[t] = acc * (1.0f / (float)Rc);   // uniform softmax weight 1/R
    }
    __syncthreads();

    // ---------------- pass AB: a0 -> b1 -> softmax -> s1 -> v1 -> a1 -> b2 -----
    float blog[BT][KR];
#pragma unroll
    for (int b = 0; b < BT; b++) {
        // v0 = squash(s0[b]) — computed redundantly per thread (cheap)
        float ss[Oc];
        float sq = 0.f;
#pragma unroll
        for (int o = 0; o < Oc; o++) { ss[o] = sred[b * 8 + o]; sq += ss[o] * ss[o]; }
        float scl = sqrtf(sq) / (1.f + sq);
        float v0[Oc];
#pragma unroll
        for (int o = 0; o < Oc; o++) v0[o] = ss[o] * scl;

        // load u_hat rows, a0, local max
        float uh[KR][Oc];
        float a0[KR];
        float mloc = -1e30f;
#pragma unroll
        for (int k = 0; k < KR; k++) {
            const int r = t + k * TT;
            const float4 A = uh4[(b * 2 + 0) * Rc + r];
            const float4 Bq = uh4[(b * 2 + 1) * Rc + r];
            uh[k][0] = A.x; uh[k][1] = A.y; uh[k][2] = A.z; uh[k][3] = A.w;
            uh[k][4] = Bq.x; uh[k][5] = Bq.y; uh[k][6] = Bq.z; uh[k][7] = Bq.w;
            float a = 0.f;
#pragma unroll
            for (int o = 0; o < Oc; o++) a += uh[k][o] * v0[o];
            a0[k] = a;
            mloc = fmaxf(mloc, a);
        }
        mloc = wmax(mloc);
        if (lane == 0) rmax[warp] = mloc;
        __syncthreads();                         // bar 1
        float m = rmax[0];
#pragma unroll
        for (int w2 = 1; w2 < NW; w2++) m = fmaxf(m, rmax[w2]);

        // weighted sums: p[0..7]=sum t*uh, p[8]=sum t
        float p[9];
#pragma unroll
        for (int q = 0; q < 9; q++) p[q] = 0.f;
#pragma unroll
        for (int k = 0; k < KR; k++) {
            const float e = expf(a0[k] - m);
            p[8] += e;
#pragma unroll
            for (int o = 0; o < Oc; o++) p[o] += e * uh[k][o];
        }
#pragma unroll
        for (int q = 0; q < 9; q++) {
            const float v = wsum(p[q]);
            if (lane == 0) rsum[warp * 10 + q] = v;
        }
        __syncthreads();                         // bar 2
        float s1[Oc];
        float st = 0.f;
#pragma unroll
        for (int o = 0; o < Oc; o++) s1[o] = 0.f;
#pragma unroll
        for (int w2 = 0; w2 < NW; w2++) {
#pragma unroll
            for (int o = 0; o < Oc; o++) s1[o] += rsum[w2 * 10 + o];
            st += rsum[w2 * 10 + 8];
        }
        const float inv = 1.f / st;
        sq = 0.f;
#pragma unroll
        for (int o = 0; o < Oc; o++) { s1[o] *= inv; sq += s1[o] * s1[o]; }
        scl = sqrtf(sq) / (1.f + sq);
        float v1[Oc];
#pragma unroll
        for (int o = 0; o < Oc; o++) v1[o] = s1[o] * scl;

        // a1 from registers; b2 = a0 + a1 (b starts at zero)
#pragma unroll
        for (int k = 0; k < KR; k++) {
            float a = 0.f;
#pragma unroll
            for (int o = 0; o < Oc; o++) a += uh[k][o] * v1[o];
            blog[b][k] = a0[k] + a;
        }
    }

    // ---------------- pass C: softmax(b2) -> s2 -> v2 -> out -------------------
#pragma unroll
    for (int b = 0; b < BT; b++) {
        float lg[KR];
        float mloc = -1e30f;
#pragma unroll
        for (int k = 0; k < KR; k++) { lg[k] = blog[b][k]; mloc = fmaxf(mloc, lg[k]); }
        mloc = wmax(mloc);
        if (lane == 0) rmax[warp] = mloc;
        __syncthreads();
        float m = rmax[0];
#pragma unroll
        for (int w2 = 1; w2 < NW; w2++) m = fmaxf(m, rmax[w2]);

        float p[9];
#pragma unroll
        for (int q = 0; q < 9; q++) p[q] = 0.f;
#pragma unroll
        for (int k = 0; k < KR; k++) {
            const int r = t + k * TT;
            const float4 A = uh4[(b * 2 + 0) * Rc + r];
            const float4 Bq = uh4[(b * 2 + 1) * Rc + r];
            const float e = expf(lg[k] - m);
            p[8] += e;
            p[0] += e * A.x; p[1] += e * A.y; p[2] += e * A.z; p[3] += e * A.w;
            p[4] += e * Bq.x; p[5] += e * Bq.y; p[6] += e * Bq.z; p[7] += e * Bq.w;
        }
#pragma unroll
        for (int q = 0; q < 9; q++) {
            const float v = wsum(p[q]);
            if (lane == 0) rsum[warp * 10 + q] = v;
        }
        __syncthreads();
        float s2[Oc];
        float st = 0.f;
#pragma unroll
        for (int o = 0; o < Oc; o++) s2[o] = 0.f;
#pragma unroll
        for (int w2 = 0; w2 < NW; w2++) {
#pragma unroll
            for (int o = 0; o < Oc; o++) s2[o] += rsum[w2 * 10 + o];
            st += rsum[w2 * 10 + 8];
        }
        const float inv = 1.f / st;
        float sq = 0.f;
#pragma unroll
        for (int o = 0; o < Oc; o++) { s2[o] *= inv; sq += s2[o] * s2[o]; }
        const float scl = sqrtf(sq) / (1.f + sq);

        if (t < Oc)
            out[((size_t)(b0 + b) * Jc + j) * Oc + t] = s2[t] * scl;
    }
}

extern "C" void kernel_launch(void* const* d_in, const int* in_sizes, int n_in,
                              void* d_out, int out_size)
{
    const float* u = (const float*)d_in[0];
    const float* W = (const float*)d_in[1];
    // defensive: u has 442368 elems, W has 4589568 — swap if order differs
    if (n_in >= 2 && in_sizes[0] > in_sizes[1]) {
        const float* tmp = u; u = W; W = tmp;
    }

    cudaFuncSetAttribute(digitcaps_kernel,
                         cudaFuncAttributeMaxDynamicSharedMemorySize, SMEM_BYTES);

    dim3 grid(Jc, Bc / BT);   // (166, 16)
    digitcaps_kernel<<<grid, TT, SMEM_BYTES>>>(u, W, (float*)d_out);
}

// round 2
// speedup vs baseline: 1.4284x; 1.4284x over previous
#include <cuda_runtime.h>
#include <math.h>

// Problem constants
#define Jc 166
#define Rc 864
#define Oc 8
#define Bc 128
#define BT 4            // batches per CTA
#define TT 288          // threads per CTA (864 / 3)
#define KR 3            // routes per thread
#define NW 9            // warps per CTA

// smem layout (floats)
#define UH_FLOATS   (BT * 2 * Rc * 4)          // 27648 floats = 110592 B
#define RED_OFF     (UH_FLOATS)
#define RED_STRIDE  40                          // per-warp partial row (36 used)
#define VF_OFF      (RED_OFF + NW * RED_STRIDE) // v vectors [BT][8], 16B aligned
#define SMEM_FLOATS (VF_OFF + BT * 8)
#define SMEM_BYTES  (SMEM_FLOATS * 4)

__device__ __forceinline__ float wsum(float v) {
#pragma unroll
    for (int s = 16; s; s >>= 1) v += __shfl_xor_sync(0xffffffffu, v, s);
    return v;
}

__global__ void __launch_bounds__(TT, 2)
digitcaps_kernel(const float* __restrict__ u,
                 const float* __restrict__ W,
                 float* __restrict__ out)
{
    extern __shared__ float sm[];
    float4* uh4 = (float4*)sm;                 // [BT*2*Rc] float4
    float*  red = sm + RED_OFF;                // [NW][RED_STRIDE]
    float*  vf  = sm + VF_OFF;                 // [BT][8]
    float4* vf4 = (float4*)vf;

    const int g    = blockIdx.x;               // batch group
    const int j    = blockIdx.y;
    const int b0   = g * BT;
    const int t    = threadIdx.x;
    const int warp = t >> 5;
    const int lane = t & 31;

    const float4* __restrict__ Wj = ((const float4*)W) + (size_t)j * (Rc * Oc);
    const float4* __restrict__ u4 = (const float4*)u;

    // ================= gen: u_hat -> smem, fused s0 partials =================
    float s0[BT][Oc];
#pragma unroll
    for (int b = 0; b < BT; b++)
#pragma unroll
        for (int o = 0; o < Oc; o++) s0[b][o] = 0.f;

#pragma unroll
    for (int k = 0; k < KR; k++) {
        const int r = t + k * TT;
        float4 w[Oc];
#pragma unroll
        for (int o = 0; o < Oc; o++) w[o] = Wj[(size_t)r * Oc + o];
#pragma unroll
        for (int b = 0; b < BT; b++) {
            const float4 uu = u4[(size_t)(b0 + b) * Rc + r];
            float h[Oc];
#pragma unroll
            for (int o = 0; o < Oc; o++)
                h[o] = w[o].x * uu.x + w[o].y * uu.y + w[o].z * uu.z + w[o].w * uu.w;
            uh4[(b * 2 + 0) * Rc + r] = make_float4(h[0], h[1], h[2], h[3]);
            uh4[(b * 2 + 1) * Rc + r] = make_float4(h[4], h[5], h[6], h[7]);
#pragma unroll
            for (int o = 0; o < Oc; o++) s0[b][o] += h[o];
        }
    }

#pragma unroll
    for (int b = 0; b < BT; b++)
#pragma unroll
        for (int o = 0; o < Oc; o++) {
            const float v = wsum(s0[b][o]);
            if (lane == 0) red[warp * RED_STRIDE + b * 8 + o] = v;
        }
    __syncthreads();                                           // bar 1

    // warp b: combine 9 partials, squash -> v0[b]
    if (warp < BT) {
        const int b = warp;
        float tot = 0.f;
        if (lane < 8)
#pragma unroll
            for (int w2 = 0; w2 < NW; w2++) tot += red[w2 * RED_STRIDE + b * 8 + lane];
        const float s = tot * (1.0f / (float)Rc);
        float sq = (lane < 8) ? s * s : 0.f;
        sq += __shfl_xor_sync(0xffffffffu, sq, 1);
        sq += __shfl_xor_sync(0xffffffffu, sq, 2);
        sq += __shfl_xor_sync(0xffffffffu, sq, 4);
        const float scl = sqrtf(sq) / (1.f + sq);
        if (lane < 8) vf[b * 8 + lane] = s * scl;
    }
    __syncthreads();                                           // bar 2

    // ======== pass 1: a0 = uh.v0; e=exp(a0) (no max needed); p-sums ==========
    float a0[BT][KR];
    float p[BT][9];
#pragma unroll
    for (int b = 0; b < BT; b++)
#pragma unroll
        for (int q = 0; q < 9; q++) p[b][q] = 0.f;

#pragma unroll
    for (int b = 0; b < BT; b++) {
        const float4 va = vf4[b * 2 + 0];
        const float4 vb = vf4[b * 2 + 1];
#pragma unroll
        for (int k = 0; k < KR; k++) {
            const int r = t + k * TT;
            const float4 A  = uh4[(b * 2 + 0) * Rc + r];
            const float4 Bq = uh4[(b * 2 + 1) * Rc + r];
            const float a = A.x * va.x + A.y * va.y + A.z * va.z + A.w * va.w
                          + Bq.x * vb.x + Bq.y * vb.y + Bq.z * vb.z + Bq.w * vb.w;
            a0[b][k] = a;
            const float e = __expf(a);
            p[b][8] += e;
            p[b][0] += e * A.x;  p[b][1] += e * A.y;
            p[b][2] += e * A.z;  p[b][3] += e * A.w;
            p[b][4] += e * Bq.x; p[b][5] += e * Bq.y;
            p[b][6] += e * Bq.z; p[b][7] += e * Bq.w;
        }
    }
#pragma unroll
    for (int b = 0; b < BT; b++)
#pragma unroll
        for (int q = 0; q < 9; q++) {
            const float v = wsum(p[b][q]);
            if (lane == 0) red[warp * RED_STRIDE + b * 9 + q] = v;
        }
    __syncthreads();                                           // bar 3

    // warp b: combine, normalize, squash -> v1[b]
    if (warp < BT) {
        const int b = warp;
        float tot = 0.f;
        if (lane < 9)
#pragma unroll
            for (int w2 = 0; w2 < NW; w2++) tot += red[w2 * RED_STRIDE + b * 9 + lane];
        const float st = __shfl_sync(0xffffffffu, tot, 8);
        const float s = tot / st;
        float sq = (lane < 8) ? s * s : 0.f;
        sq += __shfl_xor_sync(0xffffffffu, sq, 1);
        sq += __shfl_xor_sync(0xffffffffu, sq, 2);
        sq += __shfl_xor_sync(0xffffffffu, sq, 4);
        const float scl = sqrtf(sq) / (1.f + sq);
        if (lane < 8) vf[b * 8 + lane] = s * scl;
    }
    __syncthreads();                                           // bar 4

    // ==== pass 2 (fused): a1 = uh.v1; b2 = a0+a1; e=exp(b2); p2-sums =========
    float p2[BT][9];
#pragma unroll
    for (int b = 0; b < BT; b++)
#pragma unroll
        for (int q = 0; q < 9; q++) p2[b][q] = 0.f;

#pragma unroll
    for (int b = 0; b < BT; b++) {
        const float4 va = vf4[b * 2 + 0];
        const float4 vb = vf4[b * 2 + 1];
#pragma unroll
        for (int k = 0; k < KR; k++) {
            const int r = t + k * TT;
            const float4 A  = uh4[(b * 2 + 0) * Rc + r];
            const float4 Bq = uh4[(b * 2 + 1) * Rc + r];
            const float a1 = A.x * va.x + A.y * va.y + A.z * va.z + A.w * va.w
                           + Bq.x * vb.x + Bq.y * vb.y + Bq.z * vb.z + Bq.w * vb.w;
            const float e = __expf(a0[b][k] + a1);
            p2[b][8] += e;
            p2[b][0] += e * A.x;  p2[b][1] += e * A.y;
            p2[b][2] += e * A.z;  p2[b][3] += e * A.w;
            p2[b][4] += e * Bq.x; p2[b][5] += e * Bq.y;
            p2[b][6] += e * Bq.z; p2[b][7] += e * Bq.w;
        }
    }
#pragma unroll
    for (int b = 0; b < BT; b++)
#pragma unroll
        for (int q = 0; q < 9; q++) {
            const float v = wsum(p2[b][q]);
            if (lane == 0) red[warp * RED_STRIDE + b * 9 + q] = v;
        }
    __syncthreads();                                           // bar 5

    // warp b: final combine, squash, write output directly
    if (warp < BT) {
        const int b = warp;
        float tot = 0.f;
        if (lane < 9)
#pragma unroll
            for (int w2 = 0; w2 < NW; w2++) tot += red[w2 * RED_STRIDE + b * 9 + lane];
        const float st = __shfl_sync(0xffffffffu, tot, 8);
        const float s = tot / st;
        float sq = (lane < 8) ? s * s : 0.f;
        sq += __shfl_xor_sync(0xffffffffu, sq, 1);
        sq += __shfl_xor_sync(0xffffffffu, sq, 2);
        sq += __shfl_xor_sync(0xffffffffu, sq, 4);
        const float scl = sqrtf(sq) / (1.f + sq);
        if (lane < 8)
            out[((size_t)(b0 + b) * Jc + j) * Oc + lane] = s * scl;
    }
}

extern "C" void kernel_launch(void* const* d_in, const int* in_sizes, int n_in,
                              void* d_out, int out_size)
{
    const float* u = (const float*)d_in[0];
    const float* W = (const float*)d_in[1];
    if (n_in >= 2 && in_sizes[0] > in_sizes[1]) {   // defensive order check
        const float* tmp = u; u = W; W = tmp;
    }

    cudaFuncSetAttribute(digitcaps_kernel,
                         cudaFuncAttributeMaxDynamicSharedMemorySize, SMEM_BYTES);

    dim3 grid(Bc / BT, Jc);   // (32, 166): batch-group fast => same-j CTAs concurrent, W hits L2
    digitcaps_kernel<<<grid, TT, SMEM_BYTES>>>(u, W, (float*)d_out);
}

// round 3
// speedup vs baseline: 1.6074x; 1.1253x over previous
#include <cuda_runtime.h>
#include <cuda_fp16.h>
#include <math.h>

// Problem constants
#define Jc 166
#define Rc 864
#define Oc 8
#define Bc 128
#define BT 4            // batches per CTA
#define TT 288          // threads per CTA (864/3)
#define KR 3            // routes per thread
#define NW 9            // warps per CTA

// smem layout
#define UH_U4       (BT * Rc)                   // u_hat: uint4 (8 fp16) per (b,r)
#define RED_OFF     (UH_U4 * 4)                 // in floats
#define RED_STRIDE  40                          // per-warp partial row
#define VF_OFF      (RED_OFF + NW * RED_STRIDE)
#define SMEM_FLOATS (VF_OFF + BT * 8)
#define SMEM_BYTES  (SMEM_FLOATS * 4)           // ~56.9 KB -> 3 CTAs/SM

__device__ __forceinline__ float wsum(float v) {
#pragma unroll
    for (int s = 16; s; s >>= 1) v += __shfl_xor_sync(0xffffffffu, v, s);
    return v;
}
__device__ __forceinline__ unsigned int pk2(float a, float b) {
    __half2 h = __floats2half2_rn(a, b);
    return *reinterpret_cast<unsigned int*>(&h);
}
__device__ __forceinline__ float2 up2(unsigned int v) {
    __half2 h = *reinterpret_cast<__half2*>(&v);
    return __half22float2(h);
}

__global__ void __launch_bounds__(TT, 3)
digitcaps_kernel(const float* __restrict__ u,
                 const float* __restrict__ W,
                 float* __restrict__ out)
{
    extern __shared__ float sm[];
    uint4* uh  = (uint4*)sm;                   // [BT*Rc]
    float* red = sm + RED_OFF;                 // [NW][RED_STRIDE]
    float* vf  = sm + VF_OFF;                  // [BT][8]
    float4* vf4 = (float4*)vf;

    const int g    = blockIdx.x;
    const int j    = blockIdx.y;
    const int b0   = g * BT;
    const int t    = threadIdx.x;
    const int warp = t >> 5;
    const int lane = t & 31;

    const float4* __restrict__ Wj = ((const float4*)W) + (size_t)j * (Rc * Oc);
    const float4* __restrict__ u4 = (const float4*)u;

    // ================= gen: u_hat -> smem (fp16 packed) =======================
#pragma unroll
    for (int k = 0; k < KR; k++) {
        const int r = t + k * TT;
        float4 w[Oc];
#pragma unroll
        for (int o = 0; o < Oc; o++) w[o] = Wj[(size_t)r * Oc + o];
#pragma unroll
        for (int b = 0; b < BT; b++) {
            const float4 uu = u4[(size_t)(b0 + b) * Rc + r];
            float h[Oc];
#pragma unroll
            for (int o = 0; o < Oc; o++)
                h[o] = w[o].x * uu.x + w[o].y * uu.y + w[o].z * uu.z + w[o].w * uu.w;
            uint4 pkv;
            pkv.x = pk2(h[0], h[1]);
            pkv.y = pk2(h[2], h[3]);
            pkv.z = pk2(h[4], h[5]);
            pkv.w = pk2(h[6], h[7]);
            uh[b * Rc + r] = pkv;
        }
    }
    __syncthreads();                                           // bar 1

    // ================= pass0: s0 = sum_r u_hat ================================
    {
        float s0[BT][Oc];
#pragma unroll
        for (int b = 0; b < BT; b++)
#pragma unroll
            for (int o = 0; o < Oc; o++) s0[b][o] = 0.f;
#pragma unroll
        for (int b = 0; b < BT; b++)
#pragma unroll
            for (int k = 0; k < KR; k++) {
                const uint4 v = uh[b * Rc + t + k * TT];
                const float2 f0 = up2(v.x), f1 = up2(v.y), f2 = up2(v.z), f3 = up2(v.w);
                s0[b][0] += f0.x; s0[b][1] += f0.y;
                s0[b][2] += f1.x; s0[b][3] += f1.y;
                s0[b][4] += f2.x; s0[b][5] += f2.y;
                s0[b][6] += f3.x; s0[b][7] += f3.y;
            }
#pragma unroll
        for (int b = 0; b < BT; b++)
#pragma unroll
            for (int o = 0; o < Oc; o++) {
                const float v = wsum(s0[b][o]);
                if (lane == 0) red[warp * RED_STRIDE + b * 8 + o] = v;
            }
    }
    __syncthreads();                                           // bar 2
    if (warp < BT) {
        const int b = warp;
        float tot = 0.f;
        if (lane < 8)
#pragma unroll
            for (int w2 = 0; w2 < NW; w2++) tot += red[w2 * RED_STRIDE + b * 8 + lane];
        const float s = tot * (1.0f / (float)Rc);
        float sq = (lane < 8) ? s * s : 0.f;
        sq += __shfl_xor_sync(0xffffffffu, sq, 1);
        sq += __shfl_xor_sync(0xffffffffu, sq, 2);
        sq += __shfl_xor_sync(0xffffffffu, sq, 4);
        const float scl = sqrtf(sq) / (1.f + sq);
        if (lane < 8) vf[b * 8 + lane] = s * scl;
    }
    __syncthreads();                                           // bar 3

    // ===== pass1: a0=uh.v0, e=exp(a0), weighted sums (no softmax max) =========
    float a0[BT][KR];
#pragma unroll
    for (int b = 0; b < BT; b++) {
        const float4 va = vf4[b * 2 + 0];
        const float4 vb = vf4[b * 2 + 1];
        float p[9];
#pragma unroll
        for (int q = 0; q < 9; q++) p[q] = 0.f;
#pragma unroll
        for (int k = 0; k < KR; k++) {
            const uint4 v = uh[b * Rc + t + k * TT];
            const float2 f0 = up2(v.x), f1 = up2(v.y), f2 = up2(v.z), f3 = up2(v.w);
            const float a = f0.x * va.x + f0.y * va.y + f1.x * va.z + f1.y * va.w
                          + f2.x * vb.x + f2.y * vb.y + f3.x * vb.z + f3.y * vb.w;
            a0[b][k] = a;
            const float e = __expf(a);
            p[8] += e;
            p[0] += e * f0.x; p[1] += e * f0.y;
            p[2] += e * f1.x; p[3] += e * f1.y;
            p[4] += e * f2.x; p[5] += e * f2.y;
            p[6] += e * f3.x; p[7] += e * f3.y;
        }
#pragma unroll
        for (int q = 0; q < 9; q++) {
            const float v = wsum(p[q]);
            if (lane == 0) red[warp * RED_STRIDE + b * 9 + q] = v;
        }
    }
    __syncthreads();                                           // bar 4
    if (warp < BT) {
        const int b = warp;
        float tot = 0.f;
        if (lane < 9)
#pragma unroll
            for (int w2 = 0; w2 < NW; w2++) tot += red[w2 * RED_STRIDE + b * 9 + lane];
        const float st = __shfl_sync(0xffffffffu, tot, 8);
        const float s = tot / st;
        float sq = (lane < 8) ? s * s : 0.f;
        sq += __shfl_xor_sync(0xffffffffu, sq, 1);
        sq += __shfl_xor_sync(0xffffffffu, sq, 2);
        sq += __shfl_xor_sync(0xffffffffu, sq, 4);
        const float scl = sqrtf(sq) / (1.f + sq);
        if (lane < 8) vf[b * 8 + lane] = s * scl;
    }
    __syncthreads();                                           // bar 5

    // ===== pass2 (fused): a1=uh.v1, b2=a0+a1, e=exp(b2), weighted sums ========
#pragma unroll
    for (int b = 0; b < BT; b++) {
        const float4 va = vf4[b * 2 + 0];
        const float4 vb = vf4[b * 2 + 1];
        float p[9];
#pragma unroll
        for (int q = 0; q < 9; q++) p[q] = 0.f;
#pragma unroll
        for (int k = 0; k < KR; k++) {
            const uint4 v = uh[b * Rc + t + k * TT];
            const float2 f0 = up2(v.x), f1 = up2(v.y), f2 = up2(v.z), f3 = up2(v.w);
            const float a1 = f0.x * va.x + f0.y * va.y + f1.x * va.z + f1.y * va.w
                           + f2.x * vb.x + f2.y * vb.y + f3.x * vb.z + f3.y * vb.w;
            const float e = __expf(a0[b][k] + a1);
            p[8] += e;
            p[0] += e * f0.x; p[1] += e * f0.y;
            p[2] += e * f1.x; p[3] += e * f1.y;
            p[4] += e * f2.x; p[5] += e * f2.y;
            p[6] += e * f3.x; p[7] += e * f3.y;
        }
#pragma unroll
        for (int q = 0; q < 9; q++) {
            const float v = wsum(p[q]);
            if (lane == 0) red[warp * RED_STRIDE + b * 9 + q] = v;
        }
    }
    __syncthreads();                                           // bar 6
    if (warp < BT) {
        const int b = warp;
        float tot = 0.f;
        if (lane < 9)
#pragma unroll
            for (int w2 = 0; w2 < NW; w2++) tot += red[w2 * RED_STRIDE + b * 9 + lane];
        const float st = __shfl_sync(0xffffffffu, tot, 8);
        const float s = tot / st;
        float sq = (lane < 8) ? s * s : 0.f;
        sq += __shfl_xor_sync(0xffffffffu, sq, 1);
        sq += __shfl_xor_sync(0xffffffffu, sq, 2);
        sq += __shfl_xor_sync(0xffffffffu, sq, 4);
        const float scl = sqrtf(sq) / (1.f + sq);
        if (lane < 8)
            out[((size_t)(b0 + b) * Jc + j) * Oc + lane] = s * scl;
    }
}

extern "C" void kernel_launch(void* const* d_in, const int* in_sizes, int n_in,
                              void* d_out, int out_size)
{
    const float* u = (const float*)d_in[0];
    const float* W = (const float*)d_in[1];
    if (n_in >= 2 && in_sizes[0] > in_sizes[1]) {
        const float* tmp = u; u = W; W = tmp;
    }

    cudaFuncSetAttribute(digitcaps_kernel,
                         cudaFuncAttributeMaxDynamicSharedMemorySize, SMEM_BYTES);

    dim3 grid(Bc / BT, Jc);   // (32, 166)
    digitcaps_kernel<<<grid, TT, SMEM_BYTES>>>(u, W, (float*)d_out);
}

// round 4
// speedup vs baseline: 3.4142x; 2.1240x over previous
#include <cuda_runtime.h>
#include <cuda_fp16.h>
#include <math.h>

// Problem constants
#define Jc 166
#define Rc 864
#define Oc 8
#define Bc 128
#define BT 8            // batches per CTA (one per warp, warps 0-7)
#define TT 288          // threads per CTA (864/3), 9 warps
#define KR 3            // routes per thread in gen
#define RW 27           // routes per lane in routing (864/32)

#define SMEM_BYTES (BT * Rc * 16)   // u_hat fp16-packed uint4: 110592 B

__device__ __forceinline__ unsigned int pk2(float a, float b) {
    __half2 h = __floats2half2_rn(a, b);
    return *reinterpret_cast<unsigned int*>(&h);
}
__device__ __forceinline__ float2 up2(unsigned int v) {
    __half2 h = *reinterpret_cast<__half2*>(&v);
    return __half22float2(h);
}

// butterfly-reduce an array of N floats across the warp (all lanes get result)
template<int N>
__device__ __forceinline__ void wredN(float* p) {
#pragma unroll
    for (int s = 16; s; s >>= 1)
#pragma unroll
        for (int q = 0; q < N; q++)
            p[q] += __shfl_xor_sync(0xffffffffu, p[q], s);
}

__global__ void __launch_bounds__(TT, 2)
digitcaps_kernel(const float* __restrict__ u,
                 const float* __restrict__ W,
                 float* __restrict__ out)
{
    extern __shared__ uint4 uh[];              // [BT][Rc]

    const int g    = blockIdx.x;
    const int j    = blockIdx.y;
    const int b0   = g * BT;
    const int t    = threadIdx.x;
    const int warp = t >> 5;
    const int lane = t & 31;

    const float4* __restrict__ Wj = ((const float4*)W) + (size_t)j * (Rc * Oc);
    const float4* __restrict__ u4 = (const float4*)u;

    // ============== gen: u_hat -> smem (fp16 packed), all 9 warps ==============
#pragma unroll
    for (int k = 0; k < KR; k++) {
        const int r = t + k * TT;
        float4 w[Oc];
#pragma unroll
        for (int o = 0; o < Oc; o++) w[o] = Wj[(size_t)r * Oc + o];
#pragma unroll
        for (int b = 0; b < BT; b++) {
            const float4 uu = u4[(size_t)(b0 + b) * Rc + r];
            float h[Oc];
#pragma unroll
            for (int o = 0; o < Oc; o++)
                h[o] = w[o].x * uu.x + w[o].y * uu.y + w[o].z * uu.z + w[o].w * uu.w;
            uint4 pkv;
            pkv.x = pk2(h[0], h[1]);
            pkv.y = pk2(h[2], h[3]);
            pkv.z = pk2(h[4], h[5]);
            pkv.w = pk2(h[6], h[7]);
            uh[b * Rc + r] = pkv;
        }
    }
    __syncthreads();        // the only barrier

    // ============== routing: warp b owns batch b, fully warp-private ===========
    if (warp < BT) {
        const uint4* __restrict__ base = uh + warp * Rc + lane;

        // ---- pass 0: s0 = mean_r u_hat ; v0 = squash(s0) ----
        float s[9];
#pragma unroll
        for (int q = 0; q < 9; q++) s[q] = 0.f;
#pragma unroll 9
        for (int i = 0; i < RW; i++) {
            const uint4 v = base[i * 32];
            const float2 f0 = up2(v.x), f1 = up2(v.y), f2 = up2(v.z), f3 = up2(v.w);
            s[0] += f0.x; s[1] += f0.y; s[2] += f1.x; s[3] += f1.y;
            s[4] += f2.x; s[5] += f2.y; s[6] += f3.x; s[7] += f3.y;
        }
        wredN<8>(s);
        float v0[Oc];
        {
            float sq = 0.f;
#pragma unroll
            for (int o = 0; o < Oc; o++) { s[o] *= (1.0f / (float)Rc); sq += s[o] * s[o]; }
            const float scl = sqrtf(sq) / (1.f + sq);
#pragma unroll
            for (int o = 0; o < Oc; o++) v0[o] = s[o] * scl;
        }

        // ---- pass 1: e = exp(<uh,v0>) ; weighted sums -> v1 ----
        float p[9];
#pragma unroll
        for (int q = 0; q < 9; q++) p[q] = 0.f;
#pragma unroll 9
        for (int i = 0; i < RW; i++) {
            const uint4 v = base[i * 32];
            const float2 f0 = up2(v.x), f1 = up2(v.y), f2 = up2(v.z), f3 = up2(v.w);
            const float a = f0.x * v0[0] + f0.y * v0[1] + f1.x * v0[2] + f1.y * v0[3]
                          + f2.x * v0[4] + f2.y * v0[5] + f3.x * v0[6] + f3.y * v0[7];
            const float e = __expf(a);
            p[8] += e;
            p[0] += e * f0.x; p[1] += e * f0.y;
            p[2] += e * f1.x; p[3] += e * f1.y;
            p[4] += e * f2.x; p[5] += e * f2.y;
            p[6] += e * f3.x; p[7] += e * f3.y;
        }
        wredN<9>(p);
        float vs[Oc];   // vs = v0 + v1  (b2 = <uh,v0> + <uh,v1> = <uh,vs>)
        {
            const float inv = 1.f / p[8];
            float sq = 0.f;
#pragma unroll
            for (int o = 0; o < Oc; o++) { p[o] *= inv; sq += p[o] * p[o]; }
            const float scl = sqrtf(sq) / (1.f + sq);
#pragma unroll
            for (int o = 0; o < Oc; o++) vs[o] = v0[o] + p[o] * scl;
        }

        // ---- pass 2: e = exp(<uh,vs>) ; weighted sums -> v2 -> out ----
#pragma unroll
        for (int q = 0; q < 9; q++) p[q] = 0.f;
#pragma unroll 9
        for (int i = 0; i < RW; i++) {
            const uint4 v = base[i * 32];
            const float2 f0 = up2(v.x), f1 = up2(v.y), f2 = up2(v.z), f3 = up2(v.w);
            const float a = f0.x * vs[0] + f0.y * vs[1] + f1.x * vs[2] + f1.y * vs[3]
                          + f2.x * vs[4] + f2.y * vs[5] + f3.x * vs[6] + f3.y * vs[7];
            const float e = __expf(a);
            p[8] += e;
            p[0] += e * f0.x; p[1] += e * f0.y;
            p[2] += e * f1.x; p[3] += e * f1.y;
            p[4] += e * f2.x; p[5] += e * f2.y;
            p[6] += e * f3.x; p[7] += e * f3.y;
        }
        wredN<9>(p);
        {
            const float inv = 1.f / p[8];
            float sq = 0.f;
#pragma unroll
            for (int o = 0; o < Oc; o++) { p[o] *= inv; sq += p[o] * p[o]; }
            const float scl = sqrtf(sq) / (1.f + sq);
            if (lane < Oc)
                out[((size_t)(b0 + warp) * Jc + j) * Oc + lane] = p[lane] * scl;
        }
    }
}

extern "C" void kernel_launch(void* const* d_in, const int* in_sizes, int n_in,
                              void* d_out, int out_size)
{
    const float* u = (const float*)d_in[0];
    const float* W = (const float*)d_in[1];
    if (n_in >= 2 && in_sizes[0] > in_sizes[1]) {
        const float* tmp = u; u = W; W = tmp;
    }

    cudaFuncSetAttribute(digitcaps_kernel,
                         cudaFuncAttributeMaxDynamicSharedMemorySize, SMEM_BYTES);

    dim3 grid(Bc / BT, Jc);   // (16, 166)
    digitcaps_kernel<<<grid, TT, SMEM_BYTES>>>(u, W, (float*)d_out);
}